// round 12
// baseline (speedup 1.0000x reference)
#include <cuda_runtime.h>
#include <cuda_fp16.h>
#include <cstdint>

// ---------------------------------------------------------------------------
// out[M,N] = in[M,K] @ W^T + bias,  W = lut[widx].
// M=8192, N=4096, K=4096 fp32.  fused prep -> fp16 scratch, cp.async +
// ldmatrix + mma.sync.m16n8k16 (fp32 acc).
// R12: R11 GEMM verbatim (plateau: 819us, tensor 55.5%); prep deepened to
// 16 elements/thread for higher MLP.
// ---------------------------------------------------------------------------

#define M_TOTAL 8192
#define N_TOTAL 4096
#define K_TOTAL 4096

#define BM 128
#define BN 256
#define BK 64
#define STAGES 4
#define NUM_KTILES (K_TOTAL / BK)   // 64

#define ROW_BYTES 128
#define A_STAGE_BYTES (BM * ROW_BYTES)               // 16384
#define B_STAGE_BYTES (BN * ROW_BYTES)               // 32768
#define STAGE_BYTES (A_STAGE_BYTES + B_STAGE_BYTES)  // 49152
#define SMEM_TOTAL (STAGES * STAGE_BYTES)            // 196608

__device__ __align__(1024) __half g_A[(size_t)M_TOTAL * K_TOTAL];
__device__ __align__(1024) __half g_W[(size_t)N_TOTAL * K_TOTAL];

// ---------------------------------------------------------------------------
// helpers
// ---------------------------------------------------------------------------
__device__ __forceinline__ uint32_t smem_u32(const void* p) {
    uint32_t a;
    asm("{ .reg .u64 t; cvta.to.shared.u64 t, %1; cvt.u32.u64 %0, t; }"
        : "=r"(a) : "l"(p));
    return a;
}
__device__ __forceinline__ void cp_async16(uint32_t dst, const void* src) {
    asm volatile("cp.async.cg.shared.global [%0], [%1], 16;"
                 :: "r"(dst), "l"(src) : "memory");
}
__device__ __forceinline__ void cp_commit() {
    asm volatile("cp.async.commit_group;" ::: "memory");
}
template <int N>
__device__ __forceinline__ void cp_wait() {
    asm volatile("cp.async.wait_group %0;" :: "n"(N) : "memory");
}
__device__ __forceinline__ void ldsm_x4(uint32_t& r0, uint32_t& r1,
                                        uint32_t& r2, uint32_t& r3, uint32_t a) {
    asm volatile("ldmatrix.sync.aligned.m8n8.x4.shared.b16 {%0,%1,%2,%3}, [%4];"
                 : "=r"(r0), "=r"(r1), "=r"(r2), "=r"(r3) : "r"(a));
}
__device__ __forceinline__ void mma16816(float* c, const uint32_t* a,
                                         uint32_t b0, uint32_t b1) {
    asm volatile(
        "mma.sync.aligned.m16n8k16.row.col.f32.f16.f16.f32 "
        "{%0,%1,%2,%3}, {%4,%5,%6,%7}, {%8,%9}, {%0,%1,%2,%3};"
        : "+f"(c[0]), "+f"(c[1]), "+f"(c[2]), "+f"(c[3])
        : "r"(a[0]), "r"(a[1]), "r"(a[2]), "r"(a[3]), "r"(b0), "r"(b1));
}

// ---------------------------------------------------------------------------
// fused prep (16 elements/thread):
// blocks [0, WBLK) dequant W, blocks [WBLK, WBLK+ABLK) convert A
// ---------------------------------------------------------------------------
#define WBLK ((int)(((size_t)N_TOTAL * K_TOTAL / 16) / 256))   // 4096
#define ABLK ((int)(((size_t)M_TOTAL * K_TOTAL / 16) / 256))   // 8192

__global__ void prep_kernel(const float* __restrict__ inp,
                            const int* __restrict__ widx,
                            const float* __restrict__ lut) {
    __shared__ float slut[256];
    int t = threadIdx.x;
    if (blockIdx.x < WBLK) {
        if (t < 256) slut[t] = lut[t];
        __syncthreads();
        size_t i = (size_t)blockIdx.x * 256 + t;   // 16 indices / thread
        int4 v0 = reinterpret_cast<const int4*>(widx)[4 * i];
        int4 v1 = reinterpret_cast<const int4*>(widx)[4 * i + 1];
        int4 v2 = reinterpret_cast<const int4*>(widx)[4 * i + 2];
        int4 v3 = reinterpret_cast<const int4*>(widx)[4 * i + 3];
        union { __half2 h[4]; uint4 u; } p0, p1;
        p0.h[0] = __floats2half2_rn(slut[v0.x], slut[v0.y]);
        p0.h[1] = __floats2half2_rn(slut[v0.z], slut[v0.w]);
        p0.h[2] = __floats2half2_rn(slut[v1.x], slut[v1.y]);
        p0.h[3] = __floats2half2_rn(slut[v1.z], slut[v1.w]);
        p1.h[0] = __floats2half2_rn(slut[v2.x], slut[v2.y]);
        p1.h[1] = __floats2half2_rn(slut[v2.z], slut[v2.w]);
        p1.h[2] = __floats2half2_rn(slut[v3.x], slut[v3.y]);
        p1.h[3] = __floats2half2_rn(slut[v3.z], slut[v3.w]);
        reinterpret_cast<uint4*>(g_W)[2 * i] = p0.u;
        reinterpret_cast<uint4*>(g_W)[2 * i + 1] = p1.u;
    } else {
        size_t i = (size_t)(blockIdx.x - WBLK) * 256 + t;   // 16 floats / thread
        float4 f0 = reinterpret_cast<const float4*>(inp)[4 * i];
        float4 f1 = reinterpret_cast<const float4*>(inp)[4 * i + 1];
        float4 f2 = reinterpret_cast<const float4*>(inp)[4 * i + 2];
        float4 f3 = reinterpret_cast<const float4*>(inp)[4 * i + 3];
        union { __half2 h[4]; uint4 u; } p0, p1;
        p0.h[0] = __floats2half2_rn(f0.x, f0.y);
        p0.h[1] = __floats2half2_rn(f0.z, f0.w);
        p0.h[2] = __floats2half2_rn(f1.x, f1.y);
        p0.h[3] = __floats2half2_rn(f1.z, f1.w);
        p1.h[0] = __floats2half2_rn(f2.x, f2.y);
        p1.h[1] = __floats2half2_rn(f2.z, f2.w);
        p1.h[2] = __floats2half2_rn(f3.x, f3.y);
        p1.h[3] = __floats2half2_rn(f3.z, f3.w);
        reinterpret_cast<uint4*>(g_A)[2 * i] = p0.u;
        reinterpret_cast<uint4*>(g_A)[2 * i + 1] = p1.u;
    }
}

// ---------------------------------------------------------------------------
// GEMM: 128x256x64 CTA tile, 16 warps (warp 64x32), 4-stage cp.async,
// double-buffered ldmatrix fragments, three syncs per ktile (R11 verbatim).
// ---------------------------------------------------------------------------
__global__ void __launch_bounds__(512, 1) gemm_hmma_kernel(
    float* __restrict__ out, const float* __restrict__ bias) {
    extern __shared__ __align__(1024) char smem[];
    const uint32_t sb = smem_u32(smem);

    const int tid = threadIdx.x;
    const int lane = tid & 31;
    const int wid = tid >> 5;
    const int warp_m = wid & 1;      // 2 m-warps * 64 = 128
    const int warp_n = wid >> 1;     // 8 n-warps * 32 = 256

    const int m0 = blockIdx.y * BM;
    const int n0 = blockIdx.x * BN;

    // cp.async mapping (512 threads)
    const int a_ld_row = tid >> 2;
    const int a_ld_c0 = (tid & 3) * 2;
    const int b_ld_row = tid >> 1;
    const int b_ld_c0 = (tid & 1) * 4;
    const __half* gA_row = g_A + (size_t)(m0 + a_ld_row) * K_TOTAL + a_ld_c0 * 8;
    const __half* gW_row = g_W + (size_t)(n0 + b_ld_row) * K_TOTAL + b_ld_c0 * 8;
    uint32_t dstA[2], dstB[4];
    #pragma unroll
    for (int j = 0; j < 2; j++) {
        int c = a_ld_c0 + j;
        dstA[j] = a_ld_row * ROW_BYTES + ((c ^ (a_ld_row & 7)) * 16);
    }
    #pragma unroll
    for (int j = 0; j < 4; j++) {
        int c = b_ld_c0 + j;
        dstB[j] = A_STAGE_BYTES + b_ld_row * ROW_BYTES + ((c ^ (b_ld_row & 7)) * 16);
    }

    auto load_stage = [&](int s, int kt) {
        uint32_t base = sb + s * STAGE_BYTES;
        const char* srcA = (const char*)(gA_row + kt * BK);
        const char* srcB = (const char*)(gW_row + kt * BK);
        #pragma unroll
        for (int j = 0; j < 2; j++) cp_async16(base + dstA[j], srcA + j * 16);
        #pragma unroll
        for (int j = 0; j < 4; j++) cp_async16(base + dstB[j], srcB + j * 16);
    };

    // ldmatrix per-lane addressing
    const int a_row = warp_m * 64 + (lane & 15);
    const int b_row = warp_n * 32 + (lane & 15);
    const int ch_hi = lane >> 4;
    const int sw = lane & 7;

    float acc[4][4][4];                    // 64 regs
    #pragma unroll
    for (int mi = 0; mi < 4; mi++)
        #pragma unroll
        for (int ni = 0; ni < 4; ni++)
            #pragma unroll
            for (int q = 0; q < 4; q++) acc[mi][ni][q] = 0.f;

    uint32_t af[2][4][4];                  // 32 regs
    uint32_t bf[2][2][4];                  // 16 regs

    auto load_frags = [&](int buf, uint32_t aBase, uint32_t bBase, int s) {
        const uint32_t csw = (((uint32_t)(2 * s + ch_hi)) ^ (uint32_t)sw) * 16;
        #pragma unroll
        for (int mi = 0; mi < 4; mi++)
            ldsm_x4(af[buf][mi][0], af[buf][mi][1], af[buf][mi][2], af[buf][mi][3],
                    aBase + mi * 16 * ROW_BYTES + csw);
        #pragma unroll
        for (int bj = 0; bj < 2; bj++)
            ldsm_x4(bf[buf][bj][0], bf[buf][bj][1], bf[buf][bj][2], bf[buf][bj][3],
                    bBase + bj * 16 * ROW_BYTES + csw);
    };
    auto do_mma = [&](int buf) {
        #pragma unroll
        for (int mi = 0; mi < 4; mi++)
            #pragma unroll
            for (int ni = 0; ni < 4; ni++) {
                int bj = ni >> 1, tb = ni & 1;
                mma16816(acc[mi][ni], af[buf][mi], bf[buf][bj][tb], bf[buf][bj][2 + tb]);
            }
    };

    // ---- prologue: stages 0..2 in flight; stage 0 ready; prefetch step 0
    #pragma unroll
    for (int s = 0; s < STAGES - 1; s++) {
        load_stage(s, s);
        cp_commit();
    }
    cp_wait<STAGES - 2>();
    __syncthreads();
    load_frags(0, sb + a_row * ROW_BYTES,
               sb + A_STAGE_BYTES + b_row * ROW_BYTES, 0);

    for (int kt = 0; kt < NUM_KTILES; kt++) {
        const uint32_t stage = sb + (kt & (STAGES - 1)) * STAGE_BYTES;
        const uint32_t aBase = stage + a_row * ROW_BYTES;
        const uint32_t bBase = stage + A_STAGE_BYTES + b_row * ROW_BYTES;

        load_frags(1, aBase, bBase, 1);
        do_mma(0);

        // sync 1 + refill ktile kt-1's slot with ktile kt+3
        __syncthreads();
        {
            int nk = kt + STAGES - 1;
            if (nk < NUM_KTILES) load_stage(nk & (STAGES - 1), nk);
            cp_commit();
        }

        load_frags(0, aBase, bBase, 2);
        do_mma(1);

        __syncthreads();   // sync 2: convoy re-phasing

        load_frags(1, aBase, bBase, 3);
        do_mma(0);

        // sync 3: stage kt+1 complete + visible; prefetch its step 0
        cp_wait<STAGES - 2>();
        __syncthreads();
        {
            const uint32_t nstage = sb + ((kt + 1) & (STAGES - 1)) * STAGE_BYTES;
            load_frags(0, nstage + a_row * ROW_BYTES,
                       nstage + A_STAGE_BYTES + b_row * ROW_BYTES, 0);
        }
        do_mma(1);
    }

    // ---- epilogue
    const int g = lane >> 2;
    const int t = lane & 3;
    const int col_base = n0 + warp_n * 32;
    #pragma unroll
    for (int ni = 0; ni < 4; ni++) {
        int n = col_base + ni * 8 + 2 * t;
        float b0 = __ldg(&bias[n]);
        float b1 = __ldg(&bias[n + 1]);
        #pragma unroll
        for (int mi = 0; mi < 4; mi++) {
            int m = m0 + warp_m * 64 + mi * 16 + g;
            float2 v0 = make_float2(acc[mi][ni][0] + b0, acc[mi][ni][1] + b1);
            float2 v1 = make_float2(acc[mi][ni][2] + b0, acc[mi][ni][3] + b1);
            *reinterpret_cast<float2*>(out + (size_t)m * N_TOTAL + n) = v0;
            *reinterpret_cast<float2*>(out + (size_t)(m + 8) * N_TOTAL + n) = v1;
        }
    }
}

// ---------------------------------------------------------------------------
// host launcher
// ---------------------------------------------------------------------------
extern "C" void kernel_launch(void* const* d_in, const int* in_sizes, int n_in,
                              void* d_out, int out_size) {
    const float* inp  = (const float*)d_in[0];
    const float* lut  = (const float*)d_in[1];
    const int*   widx = (const int*)d_in[2];
    const float* bias = (const float*)d_in[3];
    float* out = (float*)d_out;

    prep_kernel<<<WBLK + ABLK, 256>>>(inp, widx, lut);

    static bool attr_set = false;
    if (!attr_set) {
        cudaFuncSetAttribute(gemm_hmma_kernel,
                             cudaFuncAttributeMaxDynamicSharedMemorySize, SMEM_TOTAL);
        attr_set = true;
    }
    dim3 grid(N_TOTAL / BN, M_TOTAL / BM, 1);    // (16, 64)
    gemm_hmma_kernel<<<grid, 512, SMEM_TOTAL>>>(out, bias);
}

// round 13
// speedup vs baseline: 1.0422x; 1.0422x over previous
#include <cuda_runtime.h>
#include <cuda_fp16.h>
#include <cstdint>

// ---------------------------------------------------------------------------
// out[M,N] = in[M,K] @ W^T + bias,  W = lut[widx].
// M=8192, N=4096, K=4096 fp32.  fused prep -> fp16 scratch, cp.async +
// ldmatrix + mma.sync.m16n8k16 (fp32 acc).
// R13: R11 verbatim + K-loop unrolled by STAGES(=4) so stage bases fold to
// compile-time constants (less ALU/issue overhead per ktile).
// ---------------------------------------------------------------------------

#define M_TOTAL 8192
#define N_TOTAL 4096
#define K_TOTAL 4096

#define BM 128
#define BN 256
#define BK 64
#define STAGES 4
#define NUM_KTILES (K_TOTAL / BK)   // 64

#define ROW_BYTES 128
#define A_STAGE_BYTES (BM * ROW_BYTES)               // 16384
#define B_STAGE_BYTES (BN * ROW_BYTES)               // 32768
#define STAGE_BYTES (A_STAGE_BYTES + B_STAGE_BYTES)  // 49152
#define SMEM_TOTAL (STAGES * STAGE_BYTES)            // 196608

__device__ __align__(1024) __half g_A[(size_t)M_TOTAL * K_TOTAL];
__device__ __align__(1024) __half g_W[(size_t)N_TOTAL * K_TOTAL];

// ---------------------------------------------------------------------------
// helpers
// ---------------------------------------------------------------------------
__device__ __forceinline__ uint32_t smem_u32(const void* p) {
    uint32_t a;
    asm("{ .reg .u64 t; cvta.to.shared.u64 t, %1; cvt.u32.u64 %0, t; }"
        : "=r"(a) : "l"(p));
    return a;
}
__device__ __forceinline__ void cp_async16(uint32_t dst, const void* src) {
    asm volatile("cp.async.cg.shared.global [%0], [%1], 16;"
                 :: "r"(dst), "l"(src) : "memory");
}
__device__ __forceinline__ void cp_commit() {
    asm volatile("cp.async.commit_group;" ::: "memory");
}
template <int N>
__device__ __forceinline__ void cp_wait() {
    asm volatile("cp.async.wait_group %0;" :: "n"(N) : "memory");
}
__device__ __forceinline__ void ldsm_x4(uint32_t& r0, uint32_t& r1,
                                        uint32_t& r2, uint32_t& r3, uint32_t a) {
    asm volatile("ldmatrix.sync.aligned.m8n8.x4.shared.b16 {%0,%1,%2,%3}, [%4];"
                 : "=r"(r0), "=r"(r1), "=r"(r2), "=r"(r3) : "r"(a));
}
__device__ __forceinline__ void mma16816(float* c, const uint32_t* a,
                                         uint32_t b0, uint32_t b1) {
    asm volatile(
        "mma.sync.aligned.m16n8k16.row.col.f32.f16.f16.f32 "
        "{%0,%1,%2,%3}, {%4,%5,%6,%7}, {%8,%9}, {%0,%1,%2,%3};"
        : "+f"(c[0]), "+f"(c[1]), "+f"(c[2]), "+f"(c[3])
        : "r"(a[0]), "r"(a[1]), "r"(a[2]), "r"(a[3]), "r"(b0), "r"(b1));
}

// ---------------------------------------------------------------------------
// fused prep (8 elements/thread — R11 best):
// blocks [0, WBLK) dequant W, blocks [WBLK, WBLK+ABLK) convert A
// ---------------------------------------------------------------------------
#define WBLK ((int)(((size_t)N_TOTAL * K_TOTAL / 8) / 256))   // 8192
#define ABLK ((int)(((size_t)M_TOTAL * K_TOTAL / 8) / 256))   // 16384

__global__ void prep_kernel(const float* __restrict__ inp,
                            const int* __restrict__ widx,
                            const float* __restrict__ lut) {
    __shared__ float slut[256];
    int t = threadIdx.x;
    if (blockIdx.x < WBLK) {
        if (t < 256) slut[t] = lut[t];
        __syncthreads();
        size_t i = (size_t)blockIdx.x * 256 + t;   // 8 indices / thread
        int4 v0 = reinterpret_cast<const int4*>(widx)[2 * i];
        int4 v1 = reinterpret_cast<const int4*>(widx)[2 * i + 1];
        union { __half2 h[4]; uint4 u; } pk;
        pk.h[0] = __floats2half2_rn(slut[v0.x], slut[v0.y]);
        pk.h[1] = __floats2half2_rn(slut[v0.z], slut[v0.w]);
        pk.h[2] = __floats2half2_rn(slut[v1.x], slut[v1.y]);
        pk.h[3] = __floats2half2_rn(slut[v1.z], slut[v1.w]);
        reinterpret_cast<uint4*>(g_W)[i] = pk.u;
    } else {
        size_t i = (size_t)(blockIdx.x - WBLK) * 256 + t;   // 8 floats / thread
        float4 f0 = reinterpret_cast<const float4*>(inp)[2 * i];
        float4 f1 = reinterpret_cast<const float4*>(inp)[2 * i + 1];
        union { __half2 h[4]; uint4 u; } pk;
        pk.h[0] = __floats2half2_rn(f0.x, f0.y);
        pk.h[1] = __floats2half2_rn(f0.z, f0.w);
        pk.h[2] = __floats2half2_rn(f1.x, f1.y);
        pk.h[3] = __floats2half2_rn(f1.z, f1.w);
        reinterpret_cast<uint4*>(g_A)[i] = pk.u;
    }
}

// ---------------------------------------------------------------------------
// GEMM: 128x256x64 CTA tile, 16 warps (warp 64x32), 4-stage cp.async,
// double-buffered ldmatrix fragments, three syncs per ktile, K-loop
// unrolled by STAGES for constant stage addressing.
// ---------------------------------------------------------------------------
__global__ void __launch_bounds__(512, 1) gemm_hmma_kernel(
    float* __restrict__ out, const float* __restrict__ bias) {
    extern __shared__ __align__(1024) char smem[];
    const uint32_t sb = smem_u32(smem);

    const int tid = threadIdx.x;
    const int lane = tid & 31;
    const int wid = tid >> 5;
    const int warp_m = wid & 1;      // 2 m-warps * 64 = 128
    const int warp_n = wid >> 1;     // 8 n-warps * 32 = 256

    const int m0 = blockIdx.y * BM;
    const int n0 = blockIdx.x * BN;

    // cp.async mapping (512 threads)
    const int a_ld_row = tid >> 2;
    const int a_ld_c0 = (tid & 3) * 2;
    const int b_ld_row = tid >> 1;
    const int b_ld_c0 = (tid & 1) * 4;
    const __half* gA_row = g_A + (size_t)(m0 + a_ld_row) * K_TOTAL + a_ld_c0 * 8;
    const __half* gW_row = g_W + (size_t)(n0 + b_ld_row) * K_TOTAL + b_ld_c0 * 8;
    uint32_t dstA[2], dstB[4];
    #pragma unroll
    for (int j = 0; j < 2; j++) {
        int c = a_ld_c0 + j;
        dstA[j] = a_ld_row * ROW_BYTES + ((c ^ (a_ld_row & 7)) * 16);
    }
    #pragma unroll
    for (int j = 0; j < 4; j++) {
        int c = b_ld_c0 + j;
        dstB[j] = A_STAGE_BYTES + b_ld_row * ROW_BYTES + ((c ^ (b_ld_row & 7)) * 16);
    }

    auto load_stage = [&](int s, int kt) {
        uint32_t base = sb + s * STAGE_BYTES;
        const char* srcA = (const char*)(gA_row + kt * BK);
        const char* srcB = (const char*)(gW_row + kt * BK);
        #pragma unroll
        for (int j = 0; j < 2; j++) cp_async16(base + dstA[j], srcA + j * 16);
        #pragma unroll
        for (int j = 0; j < 4; j++) cp_async16(base + dstB[j], srcB + j * 16);
    };

    // ldmatrix per-lane addressing
    const int a_row = warp_m * 64 + (lane & 15);
    const int b_row = warp_n * 32 + (lane & 15);
    const int ch_hi = lane >> 4;
    const int sw = lane & 7;

    float acc[4][4][4];                    // 64 regs
    #pragma unroll
    for (int mi = 0; mi < 4; mi++)
        #pragma unroll
        for (int ni = 0; ni < 4; ni++)
            #pragma unroll
            for (int q = 0; q < 4; q++) acc[mi][ni][q] = 0.f;

    uint32_t af[2][4][4];                  // 32 regs
    uint32_t bf[2][2][4];                  // 16 regs

    auto load_frags = [&](int buf, uint32_t aBase, uint32_t bBase, int s) {
        const uint32_t csw = (((uint32_t)(2 * s + ch_hi)) ^ (uint32_t)sw) * 16;
        #pragma unroll
        for (int mi = 0; mi < 4; mi++)
            ldsm_x4(af[buf][mi][0], af[buf][mi][1], af[buf][mi][2], af[buf][mi][3],
                    aBase + mi * 16 * ROW_BYTES + csw);
        #pragma unroll
        for (int bj = 0; bj < 2; bj++)
            ldsm_x4(bf[buf][bj][0], bf[buf][bj][1], bf[buf][bj][2], bf[buf][bj][3],
                    bBase + bj * 16 * ROW_BYTES + csw);
    };
    auto do_mma = [&](int buf) {
        #pragma unroll
        for (int mi = 0; mi < 4; mi++)
            #pragma unroll
            for (int ni = 0; ni < 4; ni++) {
                int bj = ni >> 1, tb = ni & 1;
                mma16816(acc[mi][ni], af[buf][mi], bf[buf][bj][tb], bf[buf][bj][2 + tb]);
            }
    };

    // ---- prologue: stages 0..2 in flight; stage 0 ready; prefetch step 0
    #pragma unroll
    for (int s = 0; s < STAGES - 1; s++) {
        load_stage(s, s);
        cp_commit();
    }
    cp_wait<STAGES - 2>();
    __syncthreads();
    load_frags(0, sb + a_row * ROW_BYTES,
               sb + A_STAGE_BYTES + b_row * ROW_BYTES, 0);

    #pragma unroll 4
    for (int kt = 0; kt < NUM_KTILES; kt++) {
        const uint32_t stage = sb + (kt & (STAGES - 1)) * STAGE_BYTES;
        const uint32_t aBase = stage + a_row * ROW_BYTES;
        const uint32_t bBase = stage + A_STAGE_BYTES + b_row * ROW_BYTES;

        load_frags(1, aBase, bBase, 1);
        do_mma(0);

        // sync 1 + refill ktile kt-1's slot with ktile kt+3
        __syncthreads();
        {
            int nk = kt + STAGES - 1;
            if (nk < NUM_KTILES) load_stage(nk & (STAGES - 1), nk);
            cp_commit();
        }

        load_frags(0, aBase, bBase, 2);
        do_mma(1);

        __syncthreads();   // sync 2: convoy re-phasing

        load_frags(1, aBase, bBase, 3);
        do_mma(0);

        // sync 3: stage kt+1 complete + visible; prefetch its step 0
        cp_wait<STAGES - 2>();
        __syncthreads();
        {
            const uint32_t nstage = sb + ((kt + 1) & (STAGES - 1)) * STAGE_BYTES;
            load_frags(0, nstage + a_row * ROW_BYTES,
                       nstage + A_STAGE_BYTES + b_row * ROW_BYTES, 0);
        }
        do_mma(1);
    }

    // ---- epilogue
    const int g = lane >> 2;
    const int t = lane & 3;
    const int col_base = n0 + warp_n * 32;
    #pragma unroll
    for (int ni = 0; ni < 4; ni++) {
        int n = col_base + ni * 8 + 2 * t;
        float b0 = __ldg(&bias[n]);
        float b1 = __ldg(&bias[n + 1]);
        #pragma unroll
        for (int mi = 0; mi < 4; mi++) {
            int m = m0 + warp_m * 64 + mi * 16 + g;
            float2 v0 = make_float2(acc[mi][ni][0] + b0, acc[mi][ni][1] + b1);
            float2 v1 = make_float2(acc[mi][ni][2] + b0, acc[mi][ni][3] + b1);
            *reinterpret_cast<float2*>(out + (size_t)m * N_TOTAL + n) = v0;
            *reinterpret_cast<float2*>(out + (size_t)(m + 8) * N_TOTAL + n) = v1;
        }
    }
}

// ---------------------------------------------------------------------------
// host launcher
// ---------------------------------------------------------------------------
extern "C" void kernel_launch(void* const* d_in, const int* in_sizes, int n_in,
                              void* d_out, int out_size) {
    const float* inp  = (const float*)d_in[0];
    const float* lut  = (const float*)d_in[1];
    const int*   widx = (const int*)d_in[2];
    const float* bias = (const float*)d_in[3];
    float* out = (float*)d_out;

    prep_kernel<<<WBLK + ABLK, 256>>>(inp, widx, lut);

    static bool attr_set = false;
    if (!attr_set) {
        cudaFuncSetAttribute(gemm_hmma_kernel,
                             cudaFuncAttributeMaxDynamicSharedMemorySize, SMEM_TOTAL);
        attr_set = true;
    }
    dim3 grid(N_TOTAL / BN, M_TOTAL / BM, 1);    // (16, 64)
    gemm_hmma_kernel<<<grid, 512, SMEM_TOTAL>>>(out, bias);
}